// round 12
// baseline (speedup 1.0000x reference)
#include <cuda_runtime.h>
#include <math.h>

typedef unsigned long long ull;

#define Nn 4096
#define Hd 64
#define Gg 32
#define NTOPK 6
#define TWO_PI_F 6.2831853071795864769f

#define MAXC32 192
#define GRID_A 517          // 512 qkv + 1 scan/list + 4 topk CTAs

// ---------------- scratch ----------------
__device__ float g_q[Nn * Hd];                 // silu(q) * 0.125
__device__ float g_k[Nn * Hd];                 // silu(k)
__device__ float g_v[Nn * Hd];
__device__ float g_KV[Gg * NTOPK * Hd * Hd];   // per (graph, m) 64x64
__device__ float g_kvec[Gg * NTOPK * 3];
__device__ int   g_start[Gg + 1];
__device__ int   g_list32[MAXC32];             // start | g<<13 | cnt<<18
__device__ int   g_n32;

// ---------------- f32x2 helpers ----------------
__device__ __forceinline__ ull dup2(float x) {
    ull r; asm("mov.b64 %0, {%1, %1};" : "=l"(r) : "f"(x)); return r;
}
__device__ __forceinline__ void unpack2(ull a, float& x, float& y) {
    asm("mov.b64 {%0, %1}, %2;" : "=f"(x), "=f"(y) : "l"(a));
}
__device__ __forceinline__ void fma2(ull& d, ull a, ull b) {
    asm("fma.rn.f32x2 %0, %1, %2, %0;" : "+l"(d) : "l"(a), "l"(b));
}
__device__ __forceinline__ void red2(float* p, float a, float b) {
    asm volatile("red.global.add.v2.f32 [%0], {%1, %2};" :: "l"(p), "f"(a), "f"(b) : "memory");
}
__device__ __forceinline__ void cpa16(void* sdst, const void* gsrc) {
    unsigned s = (unsigned)__cvta_generic_to_shared(sdst);
    asm volatile("cp.async.cg.shared.global [%0], [%1], 16;" :: "r"(s), "l"(gsrc) : "memory");
}

// =====================================================================
// Kernel A: zero g_KV + out (all CTAs);
//   b < 512 : QKV projection + silu (16-node x 96-j tiles)
//   b == 512: batch boundary scan (coalesced) + chunk-list build
//   b >= 513: top-6 k-grid, ONE warp per graph
// =====================================================================
__global__ __launch_bounds__(256) void kA(const float* __restrict__ x,
                                          const float* __restrict__ W,
                                          const float* __restrict__ cell,
                                          const int* __restrict__ batch,
                                          float* __restrict__ out,
                                          int out_n) {
    __shared__ float wt[64 * 98];        // 25.1KB  W transposed [h][j]
    __shared__ ull   xd_raw[64 * 18];    // 9.2KB   x dup'd [h][node(16)]; reused as staging

    int b = blockIdx.x;
    int t = threadIdx.x;

    // cooperative zeroing of g_KV and out
    {
        float4 z = make_float4(0.f, 0.f, 0.f, 0.f);
        float4* kv4 = (float4*)g_KV;
        for (int i = b * 256 + t; i < Gg * NTOPK * Hd * Hd / 4; i += GRID_A * 256)
            kv4[i] = z;
        float4* o4 = (float4*)out;
        for (int i = b * 256 + t; i < out_n / 4; i += GRID_A * 256)
            o4[i] = z;
    }

    if (b >= 513) {
        // ---------- top-k CTAs: one warp per graph ----------
        int w = t >> 5, lane = t & 31;
        int gidx = (b - 513) * 8 + w;
        float ix = 1.0f / cell[gidx * 9 + 0];
        float iy = 1.0f / cell[gidx * 9 + 4];
        float iz = 1.0f / cell[gidx * 9 + 8];
        const float k2max = (TWO_PI_F / 10.0f) * (TWO_PI_F / 10.0f);
        ull keys[11];
        int nk = 0;
        for (int idx = lane; idx < 342; idx += 32) {
            int L = idx + (idx >= 171 ? 1 : 0);
            int a = L / 49 - 3;
            int bb = (L / 7) % 7 - 3;
            int c = L % 7 - 3;
            float kx = (TWO_PI_F * (float)a) * ix;
            float ky = (TWO_PI_F * (float)bb) * iy;
            float kz = (TWO_PI_F * (float)c) * iz;
            float ksq = kx * kx + ky * ky + kz * kz;
            float eff = (ksq <= k2max) ? ksq : 1e10f;
            keys[nk++] = (((ull)__float_as_uint(eff)) << 32) | (unsigned)idx;
        }
        ull prev = 0;
        for (int s = 0; s < NTOPK; s++) {
            ull best = ~0ULL;
            #pragma unroll
            for (int i = 0; i < 11; i++)
                if (i < nk) {
                    ull kk = keys[i];
                    if (kk > prev && kk < best) best = kk;
                }
            for (int off = 16; off; off >>= 1) {
                ull o = __shfl_xor_sync(0xffffffffu, best, off);
                if (o < best) best = o;
            }
            best = __shfl_sync(0xffffffffu, best, 0);
            prev = best;
            if (lane == 0) {
                int bi = (int)(best & 0xffffffffULL);
                int L = bi + (bi >= 171 ? 1 : 0);
                int a = L / 49 - 3;
                int bb = (L / 7) % 7 - 3;
                int c = L % 7 - 3;
                g_kvec[(gidx * NTOPK + s) * 3 + 0] = (TWO_PI_F * (float)a) * ix;
                g_kvec[(gidx * NTOPK + s) * 3 + 1] = (TWO_PI_F * (float)bb) * iy;
                g_kvec[(gidx * NTOPK + s) * 3 + 2] = (TWO_PI_F * (float)c) * iz;
            }
        }
        return;
    }

    if (b == 512) {
        // ---------- boundary scan (coalesced, parallel MLP) ----------
        {
            int i0 = t * 16;
            int4 v0 = ((const int4*)batch)[t * 4 + 0];
            int4 v1 = ((const int4*)batch)[t * 4 + 1];
            int4 v2 = ((const int4*)batch)[t * 4 + 2];
            int4 v3 = ((const int4*)batch)[t * 4 + 3];
            int vals[16] = { v0.x, v0.y, v0.z, v0.w, v1.x, v1.y, v1.z, v1.w,
                             v2.x, v2.y, v2.z, v2.w, v3.x, v3.y, v3.z, v3.w };
            int prev = (t == 0) ? -1 : batch[i0 - 1];
            #pragma unroll
            for (int j = 0; j < 16; j++) {
                int cur = vals[j];
                for (int g = prev + 1; g <= cur; g++) g_start[g] = i0 + j;
                prev = cur;
            }
            if (t == 255)
                for (int g = prev + 1; g <= Gg; g++) g_start[g] = Nn;
        }
        __syncthreads();
        if (t < 32) {  // parallel chunk-list build
            int n0 = g_start[t], n1 = g_start[t + 1];
            int len = n1 - n0;
            int c = (len + 31) >> 5;
            int incl = c;
            #pragma unroll
            for (int d = 1; d < 32; d <<= 1) {
                int nbr = __shfl_up_sync(0xffffffffu, incl, d);
                if (t >= d) incl += nbr;
            }
            int excl = incl - c;
            for (int i = 0; i < c; i++)
                g_list32[excl + i] = (n0 + 32 * i) | (t << 13) | (min(32, len - 32 * i) << 18);
            if (t == 31) g_n32 = incl;
        }
        return;
    }

    // ---------- QKV CTAs: 16 nodes x 96 j ----------
    int nb = b >> 1;      // node tile of 16: nodes nb*16 ..
    int jh = b & 1;       // j half

    // stage W half transposed
    for (int s = t; s < 96 * 16; s += 256) {
        int j = s >> 4, h0 = (s & 15) * 4;
        float4 wv = *(const float4*)&W[(jh * 96 + j) * 64 + h0];
        wt[(h0 + 0) * 98 + j] = wv.x;
        wt[(h0 + 1) * 98 + j] = wv.y;
        wt[(h0 + 2) * 98 + j] = wv.z;
        wt[(h0 + 3) * 98 + j] = wv.w;
    }
    // stage x dup'd [h][node]: thread -> node = t>>4, h0 = (t&15)*4
    {
        int node = t >> 4, h0 = (t & 15) * 4;
        int n = nb * 16 + node;
        float4 xa = *(const float4*)&x[n * 64 + h0];
        xd_raw[(h0 + 0) * 18 + node] = dup2(xa.x);
        xd_raw[(h0 + 1) * 18 + node] = dup2(xa.y);
        xd_raw[(h0 + 2) * 18 + node] = dup2(xa.z);
        xd_raw[(h0 + 3) * 18 + node] = dup2(xa.w);
    }
    __syncthreads();

    int ng = t & 15;        // node
    int jg = t >> 4;        // j group
    int j0 = jg * 6;

    ull acc0 = 0, acc1 = 0, acc2 = 0;

    #pragma unroll 8
    for (int h = 0; h < 64; h++) {
        ull xx = xd_raw[h * 18 + ng];
        ull w01 = *(ull*)&wt[h * 98 + j0];
        ull w23 = *(ull*)&wt[h * 98 + j0 + 2];
        ull w45 = *(ull*)&wt[h * 98 + j0 + 4];
        fma2(acc0, w01, xx);
        fma2(acc1, w23, xx);
        fma2(acc2, w45, xx);
    }
    __syncthreads();   // done reading xd_raw; reuse as staging

    // staged epilogue: silu/scale into st[node][j], j in [0,96), pad 100
    float* st = (float*)xd_raw;   // 16*100*4 = 6.4KB <= 9.2KB
    {
        ull accs[3] = { acc0, acc1, acc2 };
        #pragma unroll
        for (int jp = 0; jp < 3; jp++) {
            int jl = j0 + jp * 2;
            int jgl = jh * 96 + jl;         // even; pairs never straddle 64/128
            float v0, v1;
            unpack2(accs[jp], v0, v1);
            if (jgl < 128) {
                v0 = v0 / (1.0f + __expf(-v0));
                v1 = v1 / (1.0f + __expf(-v1));
                if (jgl < 64) { v0 *= 0.125f; v1 *= 0.125f; }
            }
            st[ng * 100 + jl]     = v0;
            st[ng * 100 + jl + 1] = v1;
        }
    }
    __syncthreads();

    // coalesced writeback: 384 float4 per CTA
    #pragma unroll
    for (int i = 0; i < 2; i++) {
        int idx = i * 256 + t;
        if (idx < 384) {
            int node = idx / 24;
            int col = (idx % 24) * 4;
            float4 val = *(const float4*)&st[node * 100 + col];
            int n = nb * 16 + node;
            if (jh == 0) {
                if (col < 64) *(float4*)&g_q[n * 64 + col] = val;
                else          *(float4*)&g_k[n * 64 + (col - 64)] = val;
            } else {
                if (col < 32) *(float4*)&g_k[n * 64 + 32 + col] = val;
                else          *(float4*)&g_v[n * 64 + (col - 32)] = val;
            }
        }
    }
}

// =====================================================================
// Kernel 3: KV accumulation. CTA = (chunk32, m); all-smem inner loop.
// =====================================================================
__global__ __launch_bounds__(256) void k_kv(const float* __restrict__ pos) {
    int chunk = blockIdx.x / NTOPK;
    int m = blockIdx.x % NTOPK;
    if (chunk >= g_n32) return;
    int meta = g_list32[chunk];
    int base = meta & 0x1FFF;
    int g = (meta >> 13) & 31;
    int cnt = meta >> 18;

    __shared__ ull   krd[32 * 64];
    __shared__ float vs[32 * 64];
    __shared__ float2 cs_s[32];

    int t = threadIdx.x;
    int eg = t & 15;
    int hg = t >> 4;

    float kvx = g_kvec[(g * NTOPK + m) * 3 + 0];
    float kvy = g_kvec[(g * NTOPK + m) * 3 + 1];
    float kvz = g_kvec[(g * NTOPK + m) * 3 + 2];

    if (t < cnt) {
        int n = base + t;
        float ph = pos[n * 3 + 0] * kvx + pos[n * 3 + 1] * kvy + pos[n * 3 + 2] * kvz;
        float sn, cn;
        sincosf(ph, &sn, &cn);
        cs_s[t] = make_float2(cn, sn);
    }
    for (int s = t; s < cnt * 16; s += 256)
        *(float4*)&vs[s * 4] = *(const float4*)&g_v[base * 64 + s * 4];
    __syncthreads();
    for (int s = t; s < cnt * 64; s += 256) {
        int nn = s >> 6, h = s & 63;
        float2 cc = cs_s[nn];
        float k1 = g_k[(base + nn) * 64 + (h & 31)];
        float k2 = g_k[(base + nn) * 64 + (h & 31) + 32];
        float kr = (h < 32) ? (k1 * cc.x - k2 * cc.y) : (k1 * cc.y + k2 * cc.x);
        krd[s] = dup2(kr);
    }
    __syncthreads();

    ull acc[4][2];
    #pragma unroll
    for (int i = 0; i < 4; i++) { acc[i][0] = 0ULL; acc[i][1] = 0ULL; }

    #pragma unroll 4
    for (int nn = 0; nn < cnt; nn++) {
        ulonglong2 ka = *(const ulonglong2*)&krd[nn * 64 + hg * 4];
        ulonglong2 kb = *(const ulonglong2*)&krd[nn * 64 + hg * 4 + 2];
        ulonglong2 vv = *(const ulonglong2*)&vs[nn * 64 + eg * 4];
        fma2(acc[0][0], ka.x, vv.x); fma2(acc[0][1], ka.x, vv.y);
        fma2(acc[1][0], ka.y, vv.x); fma2(acc[1][1], ka.y, vv.y);
        fma2(acc[2][0], kb.x, vv.x); fma2(acc[2][1], kb.x, vv.y);
        fma2(acc[3][0], kb.y, vv.x); fma2(acc[3][1], kb.y, vv.y);
    }

    float* dst = g_KV + (size_t)(g * NTOPK + m) * 4096;
    #pragma unroll
    for (int hh = 0; hh < 4; hh++) {
        float a0, a1, a2, a3;
        unpack2(acc[hh][0], a0, a1);
        unpack2(acc[hh][1], a2, a3);
        float* p = &dst[(hg * 4 + hh) * 64 + eg * 4];
        red2(p, a0, a1);
        red2(p + 2, a2, a3);
    }
}

// =====================================================================
// Kernel 4: update. CTA = (chunk32, m); grid 1152 x 128 threads.
// Warp tile 16n x 32e; thread tile 2n x 8e. red.v2 epilogue.
// =====================================================================
__global__ __launch_bounds__(128) void k_upd(const float* __restrict__ pos,
                                             float* __restrict__ out) {
    int chunk = blockIdx.x / NTOPK;
    int m = blockIdx.x % NTOPK;
    if (chunk >= g_n32) return;
    int meta = g_list32[chunk];
    int base = meta & 0x1FFF;
    int g = (meta >> 13) & 31;
    int cnt = meta >> 18;

    __shared__ float  qtile_t[64 * 33];   // [h][node]
    __shared__ ull    qrd[64 * 34];       // [h][node] dup'd
    __shared__ float  kvs[64 * 64];       // [h][e]
    __shared__ float2 cs_s[32];

    int t = threadIdx.x;
    int le = t & 3;
    int ln = (t >> 2) & 7;
    int w  = t >> 5;
    int nblk = w & 1;
    int eblk = w >> 1;
    int nbase = nblk * 16 + 2 * ln;   // local node (even)
    int ebase = eblk * 32 + le * 8;   // e base

    // cp.async stage of KV tile
    {
        const float* kvg = g_KV + (size_t)(g * NTOPK + m) * 4096;
        #pragma unroll
        for (int i = 0; i < 8; i++)
            cpa16(&kvs[(i * 128 + t) * 4], &kvg[(i * 128 + t) * 4]);
        asm volatile("cp.async.commit_group;" ::: "memory");
    }
    // stage q transposed
    {
        int node = t >> 2, h0 = (t & 3) * 16;
        int n = min(base + node, Nn - 1);
        #pragma unroll
        for (int i = 0; i < 4; i++) {
            float4 qv = *(const float4*)&g_q[n * 64 + h0 + i * 4];
            qtile_t[(h0 + i * 4 + 0) * 33 + node] = qv.x;
            qtile_t[(h0 + i * 4 + 1) * 33 + node] = qv.y;
            qtile_t[(h0 + i * 4 + 2) * 33 + node] = qv.z;
            qtile_t[(h0 + i * 4 + 3) * 33 + node] = qv.w;
        }
    }
    // cos/sin for this m
    if (t < 32) {
        float kvx = g_kvec[(g * NTOPK + m) * 3 + 0];
        float kvy = g_kvec[(g * NTOPK + m) * 3 + 1];
        float kvz = g_kvec[(g * NTOPK + m) * 3 + 2];
        int n = min(base + t, Nn - 1);
        float ph = pos[n * 3 + 0] * kvx + pos[n * 3 + 1] * kvy + pos[n * 3 + 2] * kvz;
        float sn, cn;
        sincosf(ph, &sn, &cn);
        cs_s[t] = make_float2(cn, sn);
    }
    __syncthreads();

    // build rope'd q (dup'd), [h][node]
    #pragma unroll
    for (int i = 0; i < 16; i++) {
        int s = i * 128 + t;
        int node = s & 31, h = s >> 5;
        float2 cc = cs_s[node];
        float q1 = qtile_t[(h & 31) * 33 + node];
        float q2 = qtile_t[((h & 31) + 32) * 33 + node];
        float qr = (h < 32) ? (q1 * cc.x - q2 * cc.y) : (q1 * cc.y + q2 * cc.x);
        qrd[h * 34 + node] = dup2(qr);
    }
    asm volatile("cp.async.wait_group 0;" ::: "memory");
    __syncthreads();

    // main loop: 8 independent acc chains, 3 LDS wavefronts / h / warp
    ull a00 = 0, a01 = 0, a02 = 0, a03 = 0;
    ull a10 = 0, a11 = 0, a12 = 0, a13 = 0;
    #pragma unroll 8
    for (int h = 0; h < 64; h++) {
        ulonglong2 qq = *(const ulonglong2*)&qrd[h * 34 + nbase];
        ulonglong2 ka = *(const ulonglong2*)&kvs[h * 64 + ebase];
        ulonglong2 kb = *(const ulonglong2*)&kvs[h * 64 + ebase + 4];
        fma2(a00, qq.x, ka.x); fma2(a01, qq.x, ka.y);
        fma2(a02, qq.x, kb.x); fma2(a03, qq.x, kb.y);
        fma2(a10, qq.y, ka.x); fma2(a11, qq.y, ka.y);
        fma2(a12, qq.y, kb.x); fma2(a13, qq.y, kb.y);
    }

    int na = base + nbase;
    if (nbase < cnt) {
        float x0, x1, x2, x3, x4, x5, x6, x7;
        unpack2(a00, x0, x1); unpack2(a01, x2, x3);
        unpack2(a02, x4, x5); unpack2(a03, x6, x7);
        float* p = &out[na * 64 + ebase];
        red2(p, x0, x1); red2(p + 2, x2, x3);
        red2(p + 4, x4, x5); red2(p + 6, x6, x7);
    }
    if (nbase + 1 < cnt) {
        float x0, x1, x2, x3, x4, x5, x6, x7;
        unpack2(a10, x0, x1); unpack2(a11, x2, x3);
        unpack2(a12, x4, x5); unpack2(a13, x6, x7);
        float* p = &out[(na + 1) * 64 + ebase];
        red2(p, x0, x1); red2(p + 2, x2, x3);
        red2(p + 4, x4, x5); red2(p + 6, x6, x7);
    }
}

// =====================================================================
extern "C" void kernel_launch(void* const* d_in, const int* in_sizes, int n_in,
                              void* d_out, int out_size) {
    const float* node_feat = (const float*)d_in[0];
    const float* positions = (const float*)d_in[1];
    const float* cell      = (const float*)d_in[2];
    const int*   batch     = (const int*)d_in[3];
    const float* W_qkv     = (const float*)d_in[4];
    float* out = (float*)d_out;

    kA<<<GRID_A, 256>>>(node_feat, W_qkv, cell, batch, out, out_size);
    k_kv<<<MAXC32 * NTOPK, 256>>>(positions);
    k_upd<<<MAXC32 * NTOPK, 128>>>(positions, out);
    (void)n_in; (void)in_sizes;
}

// round 13
// speedup vs baseline: 1.0508x; 1.0508x over previous
#include <cuda_runtime.h>
#include <math.h>

typedef unsigned long long ull;

#define Nn 4096
#define Hd 64
#define Gg 32
#define NTOPK 6
#define TWO_PI_F 6.2831853071795864769f

#define MAXC32 192
#define GRID_A 261          // 256 qkv + 1 scan/list + 4 topk CTAs

// ---------------- scratch ----------------
__device__ float g_q[Nn * Hd];                 // silu(q) * 0.125
__device__ float g_k[Nn * Hd];                 // silu(k)
__device__ float g_v[Nn * Hd];
__device__ float g_KV[Gg * NTOPK * Hd * Hd];   // per (graph, m) 64x64
__device__ float g_kvec[Gg * NTOPK * 3];
__device__ int   g_start[Gg + 1];
__device__ int   g_list32[MAXC32];             // start | g<<13 | cnt<<18
__device__ int   g_n32;

// ---------------- f32x2 helpers ----------------
__device__ __forceinline__ ull dup2(float x) {
    ull r; asm("mov.b64 %0, {%1, %1};" : "=l"(r) : "f"(x)); return r;
}
__device__ __forceinline__ void unpack2(ull a, float& x, float& y) {
    asm("mov.b64 {%0, %1}, %2;" : "=f"(x), "=f"(y) : "l"(a));
}
__device__ __forceinline__ void fma2(ull& d, ull a, ull b) {
    asm("fma.rn.f32x2 %0, %1, %2, %0;" : "+l"(d) : "l"(a), "l"(b));
}
__device__ __forceinline__ void red2(float* p, float a, float b) {
    asm volatile("red.global.add.v2.f32 [%0], {%1, %2};" :: "l"(p), "f"(a), "f"(b) : "memory");
}
__device__ __forceinline__ void cpa16(void* sdst, const void* gsrc) {
    unsigned s = (unsigned)__cvta_generic_to_shared(sdst);
    asm volatile("cp.async.cg.shared.global [%0], [%1], 16;" :: "r"(s), "l"(gsrc) : "memory");
}

// =====================================================================
// Kernel A: zero g_KV + out (all CTAs);
//   b < 256 : QKV projection + silu (32-node x 96-j tiles)
//   b == 256: batch boundary scan (coalesced) + chunk-list build
//   b >= 257: top-6 k-grid, ONE warp per graph
// =====================================================================
__global__ __launch_bounds__(256) void kA(const float* __restrict__ x,
                                          const float* __restrict__ W,
                                          const float* __restrict__ cell,
                                          const int* __restrict__ batch,
                                          float* __restrict__ out,
                                          int out_n) {
    __shared__ float wt[64 * 98];        // 25.1KB  W transposed [h][j]
    __shared__ ull   xd_raw[64 * 34];    // 17.4KB  x dup'd [h][node]; reused as staging

    int b = blockIdx.x;
    int t = threadIdx.x;

    // cooperative zeroing of g_KV and out
    {
        float4 z = make_float4(0.f, 0.f, 0.f, 0.f);
        float4* kv4 = (float4*)g_KV;
        for (int i = b * 256 + t; i < Gg * NTOPK * Hd * Hd / 4; i += GRID_A * 256)
            kv4[i] = z;
        float4* o4 = (float4*)out;
        for (int i = b * 256 + t; i < out_n / 4; i += GRID_A * 256)
            o4[i] = z;
    }

    if (b >= 257) {
        // ---------- top-k CTAs: one warp per graph ----------
        int w = t >> 5, lane = t & 31;
        int gidx = (b - 257) * 8 + w;
        float ix = 1.0f / cell[gidx * 9 + 0];
        float iy = 1.0f / cell[gidx * 9 + 4];
        float iz = 1.0f / cell[gidx * 9 + 8];
        const float k2max = (TWO_PI_F / 10.0f) * (TWO_PI_F / 10.0f);
        ull keys[11];
        int nk = 0;
        for (int idx = lane; idx < 342; idx += 32) {
            int L = idx + (idx >= 171 ? 1 : 0);
            int a = L / 49 - 3;
            int bb = (L / 7) % 7 - 3;
            int c = L % 7 - 3;
            float kx = (TWO_PI_F * (float)a) * ix;
            float ky = (TWO_PI_F * (float)bb) * iy;
            float kz = (TWO_PI_F * (float)c) * iz;
            float ksq = kx * kx + ky * ky + kz * kz;
            float eff = (ksq <= k2max) ? ksq : 1e10f;
            keys[nk++] = (((ull)__float_as_uint(eff)) << 32) | (unsigned)idx;
        }
        ull prev = 0;
        for (int s = 0; s < NTOPK; s++) {
            ull best = ~0ULL;
            #pragma unroll
            for (int i = 0; i < 11; i++)
                if (i < nk) {
                    ull kk = keys[i];
                    if (kk > prev && kk < best) best = kk;
                }
            for (int off = 16; off; off >>= 1) {
                ull o = __shfl_xor_sync(0xffffffffu, best, off);
                if (o < best) best = o;
            }
            best = __shfl_sync(0xffffffffu, best, 0);
            prev = best;
            if (lane == 0) {
                int bi = (int)(best & 0xffffffffULL);
                int L = bi + (bi >= 171 ? 1 : 0);
                int a = L / 49 - 3;
                int bb = (L / 7) % 7 - 3;
                int c = L % 7 - 3;
                g_kvec[(gidx * NTOPK + s) * 3 + 0] = (TWO_PI_F * (float)a) * ix;
                g_kvec[(gidx * NTOPK + s) * 3 + 1] = (TWO_PI_F * (float)bb) * iy;
                g_kvec[(gidx * NTOPK + s) * 3 + 2] = (TWO_PI_F * (float)c) * iz;
            }
        }
        return;
    }

    if (b == 256) {
        // ---------- boundary scan (coalesced, parallel MLP) ----------
        {
            int i0 = t * 16;
            int4 v0 = ((const int4*)batch)[t * 4 + 0];
            int4 v1 = ((const int4*)batch)[t * 4 + 1];
            int4 v2 = ((const int4*)batch)[t * 4 + 2];
            int4 v3 = ((const int4*)batch)[t * 4 + 3];
            int vals[16] = { v0.x, v0.y, v0.z, v0.w, v1.x, v1.y, v1.z, v1.w,
                             v2.x, v2.y, v2.z, v2.w, v3.x, v3.y, v3.z, v3.w };
            int prev = (t == 0) ? -1 : batch[i0 - 1];
            #pragma unroll
            for (int j = 0; j < 16; j++) {
                int cur = vals[j];
                for (int g = prev + 1; g <= cur; g++) g_start[g] = i0 + j;
                prev = cur;
            }
            if (t == 255)
                for (int g = prev + 1; g <= Gg; g++) g_start[g] = Nn;
        }
        __syncthreads();
        if (t < 32) {  // parallel chunk-list build
            int n0 = g_start[t], n1 = g_start[t + 1];
            int len = n1 - n0;
            int c = (len + 31) >> 5;
            int incl = c;
            #pragma unroll
            for (int d = 1; d < 32; d <<= 1) {
                int nbr = __shfl_up_sync(0xffffffffu, incl, d);
                if (t >= d) incl += nbr;
            }
            int excl = incl - c;
            for (int i = 0; i < c; i++)
                g_list32[excl + i] = (n0 + 32 * i) | (t << 13) | (min(32, len - 32 * i) << 18);
            if (t == 31) g_n32 = incl;
        }
        return;
    }

    // ---------- QKV CTAs: 32 nodes x 96 j ----------
    int nb = b >> 1;
    int jh = b & 1;

    // stage W half transposed
    for (int s = t; s < 96 * 16; s += 256) {
        int j = s >> 4, h0 = (s & 15) * 4;
        float4 wv = *(const float4*)&W[(jh * 96 + j) * 64 + h0];
        wt[(h0 + 0) * 98 + j] = wv.x;
        wt[(h0 + 1) * 98 + j] = wv.y;
        wt[(h0 + 2) * 98 + j] = wv.z;
        wt[(h0 + 3) * 98 + j] = wv.w;
    }
    // stage x dup'd [h][node]
    {
        int node = t >> 3, h0 = (t & 7) * 8;
        int n = nb * 32 + node;
        float4 xa = *(const float4*)&x[n * 64 + h0];
        float4 xb = *(const float4*)&x[n * 64 + h0 + 4];
        xd_raw[(h0 + 0) * 34 + node] = dup2(xa.x);
        xd_raw[(h0 + 1) * 34 + node] = dup2(xa.y);
        xd_raw[(h0 + 2) * 34 + node] = dup2(xa.z);
        xd_raw[(h0 + 3) * 34 + node] = dup2(xa.w);
        xd_raw[(h0 + 4) * 34 + node] = dup2(xb.x);
        xd_raw[(h0 + 5) * 34 + node] = dup2(xb.y);
        xd_raw[(h0 + 6) * 34 + node] = dup2(xb.z);
        xd_raw[(h0 + 7) * 34 + node] = dup2(xb.w);
    }
    __syncthreads();

    int ng = t & 15;
    int jg = t >> 4;
    int j0 = jg * 6;

    ull acc[3][2];
    #pragma unroll
    for (int i = 0; i < 3; i++) { acc[i][0] = 0ULL; acc[i][1] = 0ULL; }

    #pragma unroll 8
    for (int h = 0; h < 64; h++) {
        ulonglong2 xx = *(const ulonglong2*)&xd_raw[h * 34 + ng * 2];
        ull w01 = *(ull*)&wt[h * 98 + j0];
        ull w23 = *(ull*)&wt[h * 98 + j0 + 2];
        ull w45 = *(ull*)&wt[h * 98 + j0 + 4];
        fma2(acc[0][0], w01, xx.x); fma2(acc[0][1], w01, xx.y);
        fma2(acc[1][0], w23, xx.x); fma2(acc[1][1], w23, xx.y);
        fma2(acc[2][0], w45, xx.x); fma2(acc[2][1], w45, xx.y);
    }
    __syncthreads();   // done reading xd_raw; reuse as staging

    // staged epilogue: silu/scale into st[node][j], j in [0,96), pad 100
    float* st = (float*)xd_raw;
    #pragma unroll
    for (int jp = 0; jp < 3; jp++) {
        int jl = j0 + jp * 2;
        int jgl = jh * 96 + jl;         // even; pairs never straddle 64/128
        #pragma unroll
        for (int nn = 0; nn < 2; nn++) {
            float v0, v1;
            unpack2(acc[jp][nn], v0, v1);
            if (jgl < 128) {
                v0 = v0 / (1.0f + __expf(-v0));
                v1 = v1 / (1.0f + __expf(-v1));
                if (jgl < 64) { v0 *= 0.125f; v1 *= 0.125f; }
            }
            int node = ng * 2 + nn;
            st[node * 100 + jl]     = v0;
            st[node * 100 + jl + 1] = v1;
        }
    }
    __syncthreads();

    // coalesced writeback: 768 float4 per CTA, 3 per thread
    #pragma unroll
    for (int i = 0; i < 3; i++) {
        int idx = i * 256 + t;
        int node = idx / 24;
        int col = (idx % 24) * 4;
        float4 val = *(const float4*)&st[node * 100 + col];
        int n = nb * 32 + node;
        if (jh == 0) {
            if (col < 64) *(float4*)&g_q[n * 64 + col] = val;
            else          *(float4*)&g_k[n * 64 + (col - 64)] = val;
        } else {
            if (col < 32) *(float4*)&g_k[n * 64 + 32 + col] = val;
            else          *(float4*)&g_v[n * 64 + (col - 32)] = val;
        }
    }
}

// =====================================================================
// Kernel 3: KV accumulation. CTA = (chunk32, m); all-smem inner loop.
// =====================================================================
__global__ __launch_bounds__(256) void k_kv(const float* __restrict__ pos) {
    int chunk = blockIdx.x / NTOPK;
    int m = blockIdx.x % NTOPK;
    if (chunk >= g_n32) return;
    int meta = g_list32[chunk];
    int base = meta & 0x1FFF;
    int g = (meta >> 13) & 31;
    int cnt = meta >> 18;

    __shared__ ull   krd[32 * 64];
    __shared__ float vs[32 * 64];
    __shared__ float2 cs_s[32];

    int t = threadIdx.x;
    int eg = t & 15;
    int hg = t >> 4;

    float kvx = g_kvec[(g * NTOPK + m) * 3 + 0];
    float kvy = g_kvec[(g * NTOPK + m) * 3 + 1];
    float kvz = g_kvec[(g * NTOPK + m) * 3 + 2];

    if (t < cnt) {
        int n = base + t;
        float ph = pos[n * 3 + 0] * kvx + pos[n * 3 + 1] * kvy + pos[n * 3 + 2] * kvz;
        float sn, cn;
        sincosf(ph, &sn, &cn);
        cs_s[t] = make_float2(cn, sn);
    }
    for (int s = t; s < cnt * 16; s += 256)
        *(float4*)&vs[s * 4] = *(const float4*)&g_v[base * 64 + s * 4];
    __syncthreads();
    for (int s = t; s < cnt * 64; s += 256) {
        int nn = s >> 6, h = s & 63;
        float2 cc = cs_s[nn];
        float k1 = g_k[(base + nn) * 64 + (h & 31)];
        float k2 = g_k[(base + nn) * 64 + (h & 31) + 32];
        float kr = (h < 32) ? (k1 * cc.x - k2 * cc.y) : (k1 * cc.y + k2 * cc.x);
        krd[s] = dup2(kr);
    }
    __syncthreads();

    ull acc[4][2];
    #pragma unroll
    for (int i = 0; i < 4; i++) { acc[i][0] = 0ULL; acc[i][1] = 0ULL; }

    #pragma unroll 4
    for (int nn = 0; nn < cnt; nn++) {
        ulonglong2 ka = *(const ulonglong2*)&krd[nn * 64 + hg * 4];
        ulonglong2 kb = *(const ulonglong2*)&krd[nn * 64 + hg * 4 + 2];
        ulonglong2 vv = *(const ulonglong2*)&vs[nn * 64 + eg * 4];
        fma2(acc[0][0], ka.x, vv.x); fma2(acc[0][1], ka.x, vv.y);
        fma2(acc[1][0], ka.y, vv.x); fma2(acc[1][1], ka.y, vv.y);
        fma2(acc[2][0], kb.x, vv.x); fma2(acc[2][1], kb.x, vv.y);
        fma2(acc[3][0], kb.y, vv.x); fma2(acc[3][1], kb.y, vv.y);
    }

    float* dst = g_KV + (size_t)(g * NTOPK + m) * 4096;
    #pragma unroll
    for (int hh = 0; hh < 4; hh++) {
        float a0, a1, a2, a3;
        unpack2(acc[hh][0], a0, a1);
        unpack2(acc[hh][1], a2, a3);
        float* p = &dst[(hg * 4 + hh) * 64 + eg * 4];
        red2(p, a0, a1);
        red2(p + 2, a2, a3);
    }
}

// =====================================================================
// Kernel 4: update. CTA = (chunk32, m); grid 1152 x 128 threads.
// qrd built directly from global (register rope) — no qtile staging,
// smem ~34KB -> 6 CTAs/SM. Warp tile 16n x 32e; thread tile 2n x 8e.
// =====================================================================
__global__ __launch_bounds__(128) void k_upd(const float* __restrict__ pos,
                                             float* __restrict__ out) {
    int chunk = blockIdx.x / NTOPK;
    int m = blockIdx.x % NTOPK;
    if (chunk >= g_n32) return;
    int meta = g_list32[chunk];
    int base = meta & 0x1FFF;
    int g = (meta >> 13) & 31;
    int cnt = meta >> 18;

    __shared__ ull    qrd[64 * 34];       // 17.4KB [h][node] dup'd
    __shared__ float  kvs[64 * 64];       // 16KB   [h][e]
    __shared__ float2 cs_s[32];

    int t = threadIdx.x;
    int le = t & 3;
    int ln = (t >> 2) & 7;
    int w  = t >> 5;
    int nblk = w & 1;
    int eblk = w >> 1;
    int nbase = nblk * 16 + 2 * ln;   // local node (even)
    int ebase = eblk * 32 + le * 8;   // e base

    // cp.async stage of KV tile
    {
        const float* kvg = g_KV + (size_t)(g * NTOPK + m) * 4096;
        #pragma unroll
        for (int i = 0; i < 8; i++)
            cpa16(&kvs[(i * 128 + t) * 4], &kvg[(i * 128 + t) * 4]);
        asm volatile("cp.async.commit_group;" ::: "memory");
    }
    // cos/sin for this m
    if (t < 32) {
        float kvx = g_kvec[(g * NTOPK + m) * 3 + 0];
        float kvy = g_kvec[(g * NTOPK + m) * 3 + 1];
        float kvz = g_kvec[(g * NTOPK + m) * 3 + 2];
        int n = min(base + t, Nn - 1);
        float ph = pos[n * 3 + 0] * kvx + pos[n * 3 + 1] * kvy + pos[n * 3 + 2] * kvz;
        float sn, cn;
        sincosf(ph, &sn, &cn);
        cs_s[t] = make_float2(cn, sn);
    }
    __syncthreads();   // cs_s visible

    // build rope'd q (dup'd) directly from global: thread -> node = t>>2,
    // h-octet h0 = (t&3)*8 of the lower half; handles h0..h0+7 and +32.
    {
        int node = t >> 2, h0 = (t & 3) * 8;
        int n = min(base + node, Nn - 1);
        float2 cc = cs_s[node];
        float4 q1a = *(const float4*)&g_q[n * 64 + h0];
        float4 q1b = *(const float4*)&g_q[n * 64 + h0 + 4];
        float4 q2a = *(const float4*)&g_q[n * 64 + h0 + 32];
        float4 q2b = *(const float4*)&g_q[n * 64 + h0 + 36];
        float q1[8] = { q1a.x, q1a.y, q1a.z, q1a.w, q1b.x, q1b.y, q1b.z, q1b.w };
        float q2[8] = { q2a.x, q2a.y, q2a.z, q2a.w, q2b.x, q2b.y, q2b.z, q2b.w };
        #pragma unroll
        for (int i = 0; i < 8; i++) {
            qrd[(h0 + i) * 34 + node]      = dup2(q1[i] * cc.x - q2[i] * cc.y);
            qrd[(h0 + 32 + i) * 34 + node] = dup2(q1[i] * cc.y + q2[i] * cc.x);
        }
    }
    asm volatile("cp.async.wait_group 0;" ::: "memory");
    __syncthreads();   // qrd + kvs visible

    // main loop: 8 independent acc chains, 3 LDS wavefronts / h / warp
    ull a00 = 0, a01 = 0, a02 = 0, a03 = 0;
    ull a10 = 0, a11 = 0, a12 = 0, a13 = 0;
    #pragma unroll 8
    for (int h = 0; h < 64; h++) {
        ulonglong2 qq = *(const ulonglong2*)&qrd[h * 34 + nbase];
        ulonglong2 ka = *(const ulonglong2*)&kvs[h * 64 + ebase];
        ulonglong2 kb = *(const ulonglong2*)&kvs[h * 64 + ebase + 4];
        fma2(a00, qq.x, ka.x); fma2(a01, qq.x, ka.y);
        fma2(a02, qq.x, kb.x); fma2(a03, qq.x, kb.y);
        fma2(a10, qq.y, ka.x); fma2(a11, qq.y, ka.y);
        fma2(a12, qq.y, kb.x); fma2(a13, qq.y, kb.y);
    }

    int na = base + nbase;
    if (nbase < cnt) {
        float x0, x1, x2, x3, x4, x5, x6, x7;
        unpack2(a00, x0, x1); unpack2(a01, x2, x3);
        unpack2(a02, x4, x5); unpack2(a03, x6, x7);
        float* p = &out[na * 64 + ebase];
        red2(p, x0, x1); red2(p + 2, x2, x3);
        red2(p + 4, x4, x5); red2(p + 6, x6, x7);
    }
    if (nbase + 1 < cnt) {
        float x0, x1, x2, x3, x4, x5, x6, x7;
        unpack2(a10, x0, x1); unpack2(a11, x2, x3);
        unpack2(a12, x4, x5); unpack2(a13, x6, x7);
        float* p = &out[(na + 1) * 64 + ebase];
        red2(p, x0, x1); red2(p + 2, x2, x3);
        red2(p + 4, x4, x5); red2(p + 6, x6, x7);
    }
}

// =====================================================================
extern "C" void kernel_launch(void* const* d_in, const int* in_sizes, int n_in,
                              void* d_out, int out_size) {
    const float* node_feat = (const float*)d_in[0];
    const float* positions = (const float*)d_in[1];
    const float* cell      = (const float*)d_in[2];
    const int*   batch     = (const int*)d_in[3];
    const float* W_qkv     = (const float*)d_in[4];
    float* out = (float*)d_out;

    kA<<<GRID_A, 256>>>(node_feat, W_qkv, cell, batch, out, out_size);
    k_kv<<<MAXC32 * NTOPK, 256>>>(positions);
    k_upd<<<MAXC32 * NTOPK, 128>>>(positions, out);
    (void)n_in; (void)in_sizes;
}